// round 2
// baseline (speedup 1.0000x reference)
#include <cuda_runtime.h>

#define L_   512
#define B_   128
#define D_   128
#define H_   512
#define OUT_ 5
#define M_   (L_*B_)     // 65536 rows
#define N3_  (3*H_)      // 1536 cols

// Scratch (static device allocations — no cudaMalloc allowed)
__device__ float g_U [(size_t)M_ * N3_];   // 402 MB: U for current layer
__device__ float g_h1[(size_t)M_ * H_];    // 134 MB: layer-0 hidden states
__device__ float g_h2[B_ * H_];            // last-step output of layer 1

// ---------------------------------------------------------------------------
// Packed fp32x2 helpers (Blackwell FFMA2 path — 2x fp32 throughput vs FFMA)
// ---------------------------------------------------------------------------
__device__ __forceinline__ unsigned long long dup2(float x) {
    unsigned long long r;
    asm("mov.b64 %0, {%1, %1};" : "=l"(r) : "f"(x));
    return r;
}
__device__ __forceinline__ void fma2(unsigned long long& d,
                                     unsigned long long a,
                                     unsigned long long b) {
    asm("fma.rn.f32x2 %0, %1, %2, %0;" : "+l"(d) : "l"(a), "l"(b));
}

// ---------------------------------------------------------------------------
// SGEMM: C[M x N] = A[M x K] @ B[K x N], fp32, f32x2 packed inner loop.
// BM=BN=128, BK=16, 256 threads, 8x8 per thread (cols as 4 f32x2 pairs,
// pair j lives at column j*32 + tx*2 -> conflict-free LDS.64 on Bs).
// ---------------------------------------------------------------------------
template<int K>
__global__ __launch_bounds__(256, 2)
void sgemm_f32x2(const float* __restrict__ A, const float* __restrict__ Bw,
                 float* __restrict__ C, int N)
{
    __shared__ unsigned long long As2[16][129];  // duplicated A pairs, padded
    __shared__ float Bs[16][128];

    const int tid = threadIdx.x;
    const int tx  = tid & 15;    // n-group
    const int ty  = tid >> 4;    // m-group
    const int rowBase = blockIdx.y << 7;
    const int colBase = blockIdx.x << 7;

    const int arow = tid >> 2;   // 0..63 (A tile row, +64 second pass)
    const int ak4  = tid & 3;    // which float4 along k
    const int bk   = tid >> 5;   // 0..7  (B tile k-row, +8 second pass)
    const int bc4  = tid & 31;   // which float4 along n

    unsigned long long acc[8][4];
    #pragma unroll
    for (int i = 0; i < 8; i++)
        #pragma unroll
        for (int j = 0; j < 4; j++) acc[i][j] = 0ULL;

    const float* Ab = A + (size_t)rowBase * K;
    const float* Bb = Bw + colBase;

    for (int kt = 0; kt < K; kt += 16) {
        #pragma unroll
        for (int r = 0; r < 2; r++) {
            const int m = arow + r * 64;
            const float4 av = *reinterpret_cast<const float4*>(
                Ab + (size_t)m * K + kt + ak4 * 4);
            As2[ak4*4+0][m] = dup2(av.x);
            As2[ak4*4+1][m] = dup2(av.y);
            As2[ak4*4+2][m] = dup2(av.z);
            As2[ak4*4+3][m] = dup2(av.w);
        }
        #pragma unroll
        for (int r = 0; r < 2; r++) {
            const int k = bk + r * 8;
            *reinterpret_cast<float4*>(&Bs[k][bc4*4]) =
                *reinterpret_cast<const float4*>(Bb + (size_t)(kt + k) * N + bc4*4);
        }
        __syncthreads();

        #pragma unroll
        for (int k = 0; k < 16; k++) {
            unsigned long long ra[8], rb[4];
            #pragma unroll
            for (int i = 0; i < 8; i++) ra[i] = As2[k][ty*8 + i];
            const unsigned long long* bp =
                reinterpret_cast<const unsigned long long*>(&Bs[k][0]);
            #pragma unroll
            for (int j = 0; j < 4; j++) rb[j] = bp[j*16 + tx];
            #pragma unroll
            for (int i = 0; i < 8; i++)
                #pragma unroll
                for (int j = 0; j < 4; j++) fma2(acc[i][j], ra[i], rb[j]);
        }
        __syncthreads();
    }

    #pragma unroll
    for (int i = 0; i < 8; i++) {
        float* crow = C + (size_t)(rowBase + ty*8 + i) * N + colBase;
        #pragma unroll
        for (int j = 0; j < 4; j++) {
            float lo, hi;
            asm("mov.b64 {%0, %1}, %2;" : "=f"(lo), "=f"(hi) : "l"(acc[i][j]));
            *reinterpret_cast<float2*>(crow + j*32 + tx*2) = make_float2(lo, hi);
        }
    }
}

// ---------------------------------------------------------------------------
// SRU recurrence: one thread per (b, h) channel, sequential over t.
// Loads are address-independent of the carried state -> compiler can batch.
// ---------------------------------------------------------------------------
__device__ __forceinline__ float sigmoidf_(float z) {
    return 1.f / (1.f + __expf(-z));
}

__global__ void rec_kernel(const float* __restrict__ U,
                           const float* __restrict__ v,
                           const float* __restrict__ bias,
                           float* __restrict__ hout, int writeAll)
{
    const int tid = blockIdx.x * blockDim.x + threadIdx.x;  // 0..B*H-1
    const int b = tid >> 9;          // / H_
    const int h = tid & (H_ - 1);
    const float vf = v[h],      vr = v[H_ + h];
    const float bf = bias[h],   br = bias[H_ + h];
    float c = 0.f;
    float hlast = 0.f;
    #pragma unroll 4
    for (int t = 0; t < L_; t++) {
        const size_t base = ((size_t)t * B_ + b) * N3_;
        const float u0 = U[base + h];
        const float u1 = U[base + H_ + h];
        const float u2 = U[base + 2*H_ + h];
        const float f = sigmoidf_(u1 + vf * c + bf);
        const float r = sigmoidf_(u2 + vr * c + br);
        c = f * c + (1.f - f) * u0;
        const float hv = r * c;
        if (writeAll) hout[((size_t)t * B_ + b) * H_ + h] = hv;
        hlast = hv;
    }
    if (!writeAll) hout[b * H_ + h] = hlast;
}

// ---------------------------------------------------------------------------
// Final FC: out[b,o] = sum_h h2[b,h] * fc_w[o,h] + fc_b[o]   (128 x 5)
// One warp per batch row.
// ---------------------------------------------------------------------------
__global__ void fc_kernel(const float* __restrict__ h2,
                          const float* __restrict__ w,
                          const float* __restrict__ bias,
                          float* __restrict__ out)
{
    const int gtid = blockIdx.x * blockDim.x + threadIdx.x;
    const int warp = gtid >> 5;
    const int lane = gtid & 31;
    if (warp >= B_) return;
    #pragma unroll
    for (int o = 0; o < OUT_; o++) {
        float s = 0.f;
        for (int h = lane; h < H_; h += 32)
            s += h2[warp * H_ + h] * w[o * H_ + h];
        #pragma unroll
        for (int off = 16; off > 0; off >>= 1)
            s += __shfl_down_sync(0xffffffffu, s, off);
        if (lane == 0) out[warp * OUT_ + o] = s + bias[o];
    }
}

// ---------------------------------------------------------------------------
extern "C" void kernel_launch(void* const* d_in, const int* in_sizes, int n_in,
                              void* d_out, int out_size)
{
    const float* x   = (const float*)d_in[0];
    const float* W0  = (const float*)d_in[1];
    const float* v0  = (const float*)d_in[2];
    const float* b0  = (const float*)d_in[3];
    const float* W1  = (const float*)d_in[4];
    const float* v1  = (const float*)d_in[5];
    const float* b1  = (const float*)d_in[6];
    const float* fcw = (const float*)d_in[7];
    const float* fcb = (const float*)d_in[8];
    float* out = (float*)d_out;

    float *pU, *pH1, *pH2;
    cudaGetSymbolAddress((void**)&pU,  g_U);
    cudaGetSymbolAddress((void**)&pH1, g_h1);
    cudaGetSymbolAddress((void**)&pH2, g_h2);

    const dim3 gemmGrid(N3_ / 128, M_ / 128);   // (12, 512)

    // Layer 0
    sgemm_f32x2<D_><<<gemmGrid, 256>>>(x, W0, pU, N3_);
    rec_kernel<<<(B_ * H_) / 256, 256>>>(pU, v0, b0, pH1, 1);

    // Layer 1 (reuse g_U)
    sgemm_f32x2<H_><<<gemmGrid, 256>>>(pH1, W1, pU, N3_);
    rec_kernel<<<(B_ * H_) / 256, 256>>>(pU, v1, b1, pH2, 0);

    // Head
    fc_kernel<<<(B_ * 32 + 255) / 256, 256>>>(pH2, fcw, fcb, out);
}